// round 15
// baseline (speedup 1.0000x reference)
#include <cuda_runtime.h>
#include <cuda_fp16.h>
#include <mma.h>
#include <cstdint>

using namespace nvcuda;

#define SEQ    512
#define INSZ   4096
#define HID    2048
#define OUTSZ  4096
#define STEPS  30
#define G3     6144   // 3*HID

#define NB     128    // persistent CTAs (1/SM, guaranteed co-resident)
#define NT     512    // 16 warps
#define UPB    16     // hidden units per block   (2048/128)
#define RPB    48     // gate rows per block      (3*UPB)
#define ORPB   32     // output rows per block    (4096/128)

// ---------------- device globals (static scratch; no runtime allocation) ----
__device__ float   g_GI[SEQ * G3];        // Wih@x (NO bias)
__device__ __half  g_Xh[SEQ * INSZ];      // fp16 input
__device__ __half  g_Wh[G3 * INSZ];       // fp16 enc_Wih
__device__ __half  g_Woh[OUTSZ * HID];    // fp16 W_out (COLUMN-SWIZZLED rows)
// Self-synchronizing h slots: per CTA, per parity, 4x16B chunks (3 used).
// Chunk c = { 6 fp16 h values packed in 3 words, counter }. A 16B relaxed
// store/load is one L2 sector transaction: counter match => data present.
__device__ uint4   g_hslot[2][NB][4];
// Decoder (argmax|sumexp) slots: { pack_lo, pack_hi, lsum_bits, counter }.
__device__ uint4   g_pslot[2][NB];

// ---------------- helpers ---------------------------------------------------
__device__ __forceinline__ float warp_sum(float v) {
#pragma unroll
    for (int o = 16; o; o >>= 1) v += __shfl_xor_sync(0xffffffffu, v, o);
    return v;
}
__device__ __forceinline__ float sigmoidf_(float x) {
    return 1.0f / (1.0f + expf(-x));
}
__device__ __forceinline__ unsigned f2sortable(float v) {
    unsigned sb = __float_as_uint(v);
    return (sb & 0x80000000u) ? ~sb : (sb | 0x80000000u);
}
__device__ __forceinline__ float sortable2f(unsigned s) {
    return __uint_as_float((s & 0x80000000u) ? (s & 0x7FFFFFFFu) : ~s);
}
__device__ __forceinline__ uint4 ld_rlx4(const uint4* p) {
    uint4 v;
    asm volatile("ld.relaxed.gpu.global.v4.u32 {%0,%1,%2,%3}, [%4];"
                 : "=r"(v.x), "=r"(v.y), "=r"(v.z), "=r"(v.w) : "l"(p) : "memory");
    return v;
}
__device__ __forceinline__ void st_rlx4(uint4* p, uint4 v) {
    asm volatile("st.relaxed.gpu.global.v4.u32 [%0], {%1,%2,%3,%4};"
                 :: "l"(p), "r"(v.x), "r"(v.y), "r"(v.z), "r"(v.w) : "memory");
}
__device__ __forceinline__ unsigned later_u(unsigned a, unsigned b) {
    return ((int)(a - b) >= 0) ? a : b;   // handles wraparound
}

// Publish 16 h values (half bits in lanes 0..15) + counter, 3 chunks.
// All 32 lanes run the shuffles; lanes 0..2 store their chunk.
__device__ __forceinline__ void publish_h(int bid, int lane, unsigned hb,
                                          unsigned cnt, int buf) {
    unsigned w0 = 0, w1 = 0, w2 = 0;
#pragma unroll
    for (int k = 0; k < 6; k++) {
        unsigned t = __shfl_sync(0xffffffffu, hb, (lane * 6 + k) & 15);
        if (k < 2)      w0 |= (t & 0xffffu) << (16 * k);
        else if (k < 4) w1 |= (t & 0xffffu) << (16 * (k - 2));
        else            w2 |= (t & 0xffffu) << (16 * (k - 4));
    }
    if (lane < 3) st_rlx4(&g_hslot[buf][bid][lane], make_uint4(w0, w1, w2, cnt));
}

// Warp w polls chunks of its 8 producer CTAs; data arrives WITH the poll.
// Stage into SWIZZLED hstage: uint4 element e = c*32 + l holds half2 pairs
// p = l*32 + c*4 .. +3  (i.e. columns l*64 + c*8 .. +7).
__device__ __forceinline__ void poll_stage_h(int warp, int lane, unsigned base,
                                             unsigned j, __half* hstage) {
    if (lane < 24) {
        int slot = warp * 8 + lane / 3;
        int c    = lane - (lane / 3) * 3;
        const uint4* p = &g_hslot[j & 1][slot][c];
        uint4 v;
        do { v = ld_rlx4(p); } while (v.w - base < j);
        unsigned* dw = (unsigned*)hstage;
        unsigned vals[3] = {v.x, v.y, v.z};
        int pbase = slot * 8 + c * 3;
        int nk = (c == 2) ? 2 : 3;        // chunk 2 carries only pairs 6,7
#pragma unroll
        for (int k = 0; k < 3; k++) {
            if (k < nk) {
                int pp = pbase + k;
                int l = pp >> 5, rem = pp & 31;
                dw[(rem >> 2) * 128 + l * 4 + (rem & 3)] = vals[k];
            }
        }
    }
}

// One-time: warp's 3 Whh rows for this CTA -> 2 rows in REGISTERS (wr),
// 1 row in SMEM (ws16). Thread (w,l) owns columns l*64..l*64+63 of each row:
// wr[rr][q] = half2 of cols l*64 + 2q .. +1  (q = c*4+k matches h swizzle).
__device__ __forceinline__ void load_wreg(const float* __restrict__ W,
                                          __half2 (&wr)[2][32], __half* ws16,
                                          int bid, int warp, int lane) {
#pragma unroll
    for (int rr = 0; rr < 2; rr++) {
        int r48  = warp * 3 + rr;
        int grow = (r48 >> 4) * HID + bid * UPB + (r48 & 15);
        const float2* src = (const float2*)(W + (size_t)grow * HID) + lane * 32;
#pragma unroll
        for (int q = 0; q < 32; q++) {
            float2 f = __ldg(&src[q]);
            wr[rr][q] = __floats2half2_rn(f.x, f.y);
        }
    }
    {
        int r48  = warp * 3 + 2;
        int grow = (r48 >> 4) * HID + bid * UPB + (r48 & 15);
        const float2* src = (const float2*)(W + (size_t)grow * HID) + lane * 32;
        uint4* dst = (uint4*)ws16 + warp * 256;
#pragma unroll
        for (int c = 0; c < 8; c++) {
            float2 f0 = __ldg(&src[c * 4 + 0]);
            float2 f1 = __ldg(&src[c * 4 + 1]);
            float2 f2 = __ldg(&src[c * 4 + 2]);
            float2 f3 = __ldg(&src[c * 4 + 3]);
            uint4 hv;
            *(__half2*)&hv.x = __floats2half2_rn(f0.x, f0.y);
            *(__half2*)&hv.y = __floats2half2_rn(f1.x, f1.y);
            *(__half2*)&hv.z = __floats2half2_rn(f2.x, f2.y);
            *(__half2*)&hv.w = __floats2half2_rn(f3.x, f3.y);
            dst[c * 32 + lane] = hv;
        }
    }
}

// 48-row matvec: 2 rows from registers + 1 row from SMEM, h from swizzled
// SMEM stage. fp32 flush every 16 halfs (same granularity as before).
__device__ __forceinline__ void matvec_reg(const __half2 (&wr)[2][32],
                                           const __half* __restrict__ ws16,
                                           const __half* __restrict__ hstage,
                                           float* gh_s, const float* bhh_s,
                                           int warp, int lane) {
    const uint4* hu = (const uint4*)hstage;
    const uint4* wu = (const uint4*)ws16 + warp * 256;
    float a0 = 0.f, a1 = 0.f, a2 = 0.f;
#pragma unroll
    for (int cc = 0; cc < 4; cc++) {
        uint4 ha = hu[(cc * 2) * 32 + lane];
        uint4 hb = hu[(cc * 2 + 1) * 32 + lane];
        uint4 wa = wu[(cc * 2) * 32 + lane];
        uint4 wb = wu[(cc * 2 + 1) * 32 + lane];
        __half2 h0 = *(__half2*)&ha.x, h1 = *(__half2*)&ha.y;
        __half2 h2 = *(__half2*)&ha.z, h3 = *(__half2*)&ha.w;
        __half2 h4 = *(__half2*)&hb.x, h5 = *(__half2*)&hb.y;
        __half2 h6 = *(__half2*)&hb.z, h7 = *(__half2*)&hb.w;
        // row 0 (regs)
        __half2 s = __hmul2(wr[0][cc * 8 + 0], h0);
        s = __hfma2(wr[0][cc * 8 + 1], h1, s);
        s = __hfma2(wr[0][cc * 8 + 2], h2, s);
        s = __hfma2(wr[0][cc * 8 + 3], h3, s);
        s = __hfma2(wr[0][cc * 8 + 4], h4, s);
        s = __hfma2(wr[0][cc * 8 + 5], h5, s);
        s = __hfma2(wr[0][cc * 8 + 6], h6, s);
        s = __hfma2(wr[0][cc * 8 + 7], h7, s);
        float2 f = __half22float2(s);
        a0 += f.x + f.y;
        // row 1 (regs)
        s = __hmul2(wr[1][cc * 8 + 0], h0);
        s = __hfma2(wr[1][cc * 8 + 1], h1, s);
        s = __hfma2(wr[1][cc * 8 + 2], h2, s);
        s = __hfma2(wr[1][cc * 8 + 3], h3, s);
        s = __hfma2(wr[1][cc * 8 + 4], h4, s);
        s = __hfma2(wr[1][cc * 8 + 5], h5, s);
        s = __hfma2(wr[1][cc * 8 + 6], h6, s);
        s = __hfma2(wr[1][cc * 8 + 7], h7, s);
        f = __half22float2(s);
        a1 += f.x + f.y;
        // row 2 (SMEM)
        s = __hmul2(*(__half2*)&wa.x, h0);
        s = __hfma2(*(__half2*)&wa.y, h1, s);
        s = __hfma2(*(__half2*)&wa.z, h2, s);
        s = __hfma2(*(__half2*)&wa.w, h3, s);
        s = __hfma2(*(__half2*)&wb.x, h4, s);
        s = __hfma2(*(__half2*)&wb.y, h5, s);
        s = __hfma2(*(__half2*)&wb.z, h6, s);
        s = __hfma2(*(__half2*)&wb.w, h7, s);
        f = __half22float2(s);
        a2 += f.x + f.y;
    }
    a0 = warp_sum(a0);
    a1 = warp_sum(a1);
    a2 = warp_sum(a2);
    if (lane == 0) {
        gh_s[warp * 3 + 0] = a0 + bhh_s[warp * 3 + 0];
        gh_s[warp * 3 + 1] = a1 + bhh_s[warp * 3 + 1];
        gh_s[warp * 3 + 2] = a2 + bhh_s[warp * 3 + 2];
    }
}

// ---------------- fp32 -> fp16 converters -----------------------------------
__global__ void __launch_bounds__(256) conv_x_kernel(const float* __restrict__ src) {
    int i = blockIdx.x * blockDim.x + threadIdx.x;   // float4 index
    if (i < SEQ * INSZ / 4) {
        float4 v = __ldg((const float4*)src + i);
        union { __half2 h[2]; uint2 u; } cv;
        cv.h[0] = __floats2half2_rn(v.x, v.y);
        cv.h[1] = __floats2half2_rn(v.z, v.w);
        ((uint2*)g_Xh)[i] = cv.u;
    }
}
__global__ void __launch_bounds__(256) conv_w_kernel(const float* __restrict__ src) {
    int i = blockIdx.x * blockDim.x + threadIdx.x;
    if (i < G3 * INSZ / 4) {
        float4 v = __ldg((const float4*)src + i);
        union { __half2 h[2]; uint2 u; } cv;
        cv.h[0] = __floats2half2_rn(v.x, v.y);
        cv.h[1] = __floats2half2_rn(v.z, v.w);
        ((uint2*)g_Wh)[i] = cv.u;
    }
}
// W_out in COLUMN-SWIZZLED order: out uint4 e = c*32+l of row holds cols
// l*64 + c*8 .. +7 — matches the swizzled h stage element-for-element.
__global__ void __launch_bounds__(256) conv_wout_kernel(const float* __restrict__ src) {
    int i = blockIdx.x * blockDim.x + threadIdx.x;   // uint4 output index
    if (i < OUTSZ * HID / 8) {
        int row = i >> 8, e = i & 255;
        int c = e >> 5, l = e & 31;
        const float* s = src + (size_t)row * HID + l * 64 + c * 8;
        float4 f0 = __ldg((const float4*)s);
        float4 f1 = __ldg((const float4*)(s + 4));
        uint4 hv;
        *(__half2*)&hv.x = __floats2half2_rn(f0.x, f0.y);
        *(__half2*)&hv.y = __floats2half2_rn(f0.z, f0.w);
        *(__half2*)&hv.z = __floats2half2_rn(f1.x, f1.y);
        *(__half2*)&hv.w = __floats2half2_rn(f1.z, f1.w);
        ((uint4*)g_Woh)[i] = hv;
    }
}

// ---------------- kernel 1: GI = X @ Wih^T (wmma + cp.async pipeline) -------
#define KC 32
__device__ __forceinline__ void cp16(void* smem, const void* g) {
    unsigned s = (unsigned)__cvta_generic_to_shared(smem);
    asm volatile("cp.async.cg.shared.global [%0], [%1], 16;" :: "r"(s), "l"(g));
}
__global__ void __launch_bounds__(256) gemm_wmma_kernel() {
    __shared__ __half As[2][128][KC + 8];   // row stride 80B (16B-aligned)
    __shared__ __half Bs[2][128][KC + 8];

    int m0 = blockIdx.y * 128, n0 = blockIdx.x * 128;
    int t = threadIdx.x;
    int wid = t >> 5;
    int wm = wid & 1, wn = wid >> 1;        // warp tile: 64(M) x 32(N)

    wmma::fragment<wmma::accumulator, 16, 16, 16, float> c[4][2];
#pragma unroll
    for (int i = 0; i < 4; i++)
#pragma unroll
        for (int j = 0; j < 2; j++) wmma::fill_fragment(c[i][j], 0.f);

    int lrow = t >> 1;
    int lseg = (t & 1) * 16;
    const __half* ag = g_Xh + (size_t)(m0 + lrow) * INSZ + lseg;
    const __half* bg = g_Wh + (size_t)(n0 + lrow) * INSZ + lseg;

    // prologue: stage 0
    cp16(&As[0][lrow][lseg], ag);     cp16(&As[0][lrow][lseg + 8], ag + 8);
    cp16(&Bs[0][lrow][lseg], bg);     cp16(&Bs[0][lrow][lseg + 8], bg + 8);
    asm volatile("cp.async.commit_group;");

    const int NK = INSZ / KC;
    for (int kt = 0; kt < NK; kt++) {
        if (kt + 1 < NK) {
            int sb = (kt + 1) & 1;
            int k0 = (kt + 1) * KC;
            cp16(&As[sb][lrow][lseg], ag + k0);
            cp16(&As[sb][lrow][lseg + 8], ag + k0 + 8);
            cp16(&Bs[sb][lrow][lseg], bg + k0);
            cp16(&Bs[sb][lrow][lseg + 8], bg + k0 + 8);
            asm volatile("cp.async.commit_group;");
            asm volatile("cp.async.wait_group 1;");
        } else {
            asm volatile("cp.async.wait_group 0;");
        }
        __syncthreads();
        int sb = kt & 1;
#pragma unroll
        for (int kk = 0; kk < KC; kk += 16) {
            wmma::fragment<wmma::matrix_a, 16, 16, 16, __half, wmma::row_major> af[4];
            wmma::fragment<wmma::matrix_b, 16, 16, 16, __half, wmma::col_major> bf[2];
#pragma unroll
            for (int i = 0; i < 4; i++)
                wmma::load_matrix_sync(af[i], &As[sb][wm * 64 + i * 16][kk], KC + 8);
#pragma unroll
            for (int j = 0; j < 2; j++)
                wmma::load_matrix_sync(bf[j], &Bs[sb][wn * 32 + j * 16][kk], KC + 8);
#pragma unroll
            for (int i = 0; i < 4; i++)
#pragma unroll
                for (int j = 0; j < 2; j++)
                    wmma::mma_sync(c[i][j], af[i], bf[j], c[i][j]);
        }
        __syncthreads();
    }
#pragma unroll
    for (int i = 0; i < 4; i++)
#pragma unroll
        for (int j = 0; j < 2; j++)
            wmma::store_matrix_sync(
                &g_GI[(size_t)(m0 + wm * 64 + i * 16) * G3 + n0 + wn * 32 + j * 16],
                c[i][j], G3, wmma::mem_row_major);
}

// ---------------- kernel 2: persistent encoder + decoder --------------------
__global__ void __launch_bounds__(NT, 1) rnn_kernel(
    const float* __restrict__ enc_Whh, const float* __restrict__ enc_bih,
    const float* __restrict__ enc_bhh,
    const float* __restrict__ dec_Wih, const float* __restrict__ dec_Whh,
    const float* __restrict__ dec_bih, const float* __restrict__ dec_bhh,
    const float* __restrict__ b_out,
    float* __restrict__ out) {

    extern __shared__ char dyn[];
    __half* ws16   = (__half*)dyn;                         // 16 rows = 64KB
    __half* hstage = (__half*)(dyn + 16 * HID * sizeof(__half));   // 4KB

    __shared__ float gh_s[RPB];
    __shared__ float bhh_s[RPB];
    __shared__ float bih_s[RPB];
    __shared__ float ls[ORPB];
    __shared__ float red_s[3];          // gmax, lse, idx-as-bits

    int bid = blockIdx.x, tid = threadIdx.x;
    int warp = tid >> 5, lane = tid & 31;

    unsigned base  = later_u(ld_rlx4(&g_hslot[0][bid][0]).w,
                             ld_rlx4(&g_hslot[1][bid][0]).w);
    unsigned base2 = later_u(ld_rlx4(&g_pslot[0][bid]).w,
                             ld_rlx4(&g_pslot[1][bid]).w);

    // one-time: encoder weights -> 2 rows regs + 1 row SMEM; biases -> SMEM
    __half2 wr[2][32];
    load_wreg(enc_Whh, wr, ws16, bid, warp, lane);
    if (tid < RPB) {
        int grow = (tid >> 4) * HID + bid * UPB + (tid & 15);
        bhh_s[tid] = enc_bhh[grow];
        bih_s[tid] = enc_bih[grow];
    }

    float h_reg = 0.f;                  // lane u<16 of warp 0 owns h[bid*16+u]
    unsigned j = 1;

    // publish initial h = 0 with counter base+1 (parity 1)
    if (warp == 0)
        publish_h(bid, lane, __half_as_ushort(__float2half(0.f)), base + 1, 1);

    // ---------------- encoder: 512 sequential GRU steps ----------------
    for (int t = 0; t < SEQ; t++) {
        float gi0 = 0.f, gi1 = 0.f, gi2 = 0.f;
        if (warp == 0 && lane < UPB) {  // prefetch gi (independent of h)
            const float* gi = g_GI + (size_t)t * G3 + bid * UPB + lane;
            gi0 = __ldg(gi); gi1 = __ldg(gi + HID); gi2 = __ldg(gi + 2 * HID);
        }
        poll_stage_h(warp, lane, base, j, hstage);
        __syncthreads();                        // full h staged
        matvec_reg(wr, ws16, hstage, gh_s, bhh_s, warp, lane);
        __syncthreads();                        // gh_s ready
        if (warp == 0) {
            if (lane < UPB) {
                float r = sigmoidf_(gi0 + bih_s[lane]      + gh_s[lane]);
                float z = sigmoidf_(gi1 + bih_s[16 + lane] + gh_s[16 + lane]);
                float n = tanhf(    gi2 + bih_s[32 + lane]
                                        + r * gh_s[32 + lane]);
                h_reg = (1.f - z) * n + z * h_reg;
            }
            publish_h(bid, lane, __half_as_ushort(__float2half(h_reg)),
                      base + j + 1, (j + 1) & 1);
        }
        j++;
    }

    // ---------------- decoder: swap weights to dec_Whh ----------------
    __syncthreads();                    // all reads of enc ws16 finished
    load_wreg(dec_Whh, wr, ws16, bid, warp, lane);
    if (tid < RPB) {
        int grow = (tid >> 4) * HID + bid * UPB + (tid & 15);
        bhh_s[tid] = dec_bhh[grow];
    }

    int prev_idx = -1;     // first x is the zero vector
    for (int s = 0; s < STEPS; s++) {
        float gi0 = 0.f, gi1 = 0.f, gi2 = 0.f;
        if (warp == 0 && lane < UPB) {
            int u = bid * UPB + lane;
            gi0 = dec_bih[u];
            gi1 = dec_bih[HID + u];
            gi2 = dec_bih[2 * HID + u];
            if (prev_idx >= 0) {
                gi0 += __ldg(&dec_Wih[(size_t)u * INSZ + prev_idx]);
                gi1 += __ldg(&dec_Wih[(size_t)(HID + u) * INSZ + prev_idx]);
                gi2 += __ldg(&dec_Wih[(size_t)(2 * HID + u) * INSZ + prev_idx]);
            }
        }
        poll_stage_h(warp, lane, base, j, hstage);
        __syncthreads();
        matvec_reg(wr, ws16, hstage, gh_s, bhh_s, warp, lane);
        __syncthreads();
        if (warp == 0) {
            if (lane < UPB) {
                float r = sigmoidf_(gi0 + gh_s[lane]);
                float z = sigmoidf_(gi1 + gh_s[16 + lane]);
                float n = tanhf(    gi2 + r * gh_s[32 + lane]);
                h_reg = (1.f - z) * n + z * h_reg;
            }
            publish_h(bid, lane, __half_as_ushort(__float2half(h_reg)),
                      base + j + 1, (j + 1) & 1);
        }
        j++;

        // stage h^(new) for logits (same self-sync poll, swizzled)
        poll_stage_h(warp, lane, base, j, hstage);
        __syncthreads();

        // logits: 16 warps x 2 rows of swizzled fp16 W_out against swizzled h
        {
            const uint4* hp = (const uint4*)hstage;
            uint4 hreg[8];
#pragma unroll
            for (int c = 0; c < 8; c++)
                hreg[c] = hp[c * 32 + lane];
#pragma unroll
            for (int rr = 0; rr < 2; rr++) {
                int rl = warp * 2 + rr;
                int grow = bid * ORPB + rl;
                const uint4* wrow = (const uint4*)(g_Woh + (size_t)grow * HID);
                float acc = 0.f;
#pragma unroll
                for (int c = 0; c < 8; c++) {
                    uint4 w = __ldg(&wrow[lane + c * 32]);
                    __half2 sh = __hmul2(*(__half2*)&w.x, *(__half2*)&hreg[c].x);
                    sh = __hfma2(*(__half2*)&w.y, *(__half2*)&hreg[c].y, sh);
                    sh = __hfma2(*(__half2*)&w.z, *(__half2*)&hreg[c].z, sh);
                    sh = __hfma2(*(__half2*)&w.w, *(__half2*)&hreg[c].w, sh);
                    float2 f = __half22float2(sh);
                    acc += f.x + f.y;
                }
                acc = warp_sum(acc);
                if (lane == 0) ls[rl] = acc + b_out[grow];
            }
        }
        __syncthreads();                // ls ready

        // warp 0: publish self-sync pack chunk; poll all; reduce
        if (warp == 0) {
            float v = ls[lane];
            unsigned long long pack =
                ((unsigned long long)f2sortable(v) << 32) |
                (unsigned long long)(0xFFFFFFFFu - (unsigned)(bid * ORPB + lane));
#pragma unroll
            for (int o = 16; o; o >>= 1) {
                unsigned long long other = __shfl_xor_sync(0xffffffffu, pack, o);
                pack = other > pack ? other : pack;
            }
            float lmax = sortable2f((unsigned)(pack >> 32));
            float e = warp_sum(expf(v - lmax));
            unsigned s1 = s + 1;
            if (lane == 0)
                st_rlx4(&g_pslot[s1 & 1][bid],
                        make_uint4((unsigned)(pack & 0xFFFFFFFFull),
                                   (unsigned)(pack >> 32),
                                   __float_as_uint(e), base2 + s1));
            unsigned long long pk[4];
            float lsm[4];
#pragma unroll
            for (int i = 0; i < 4; i++) {
                const uint4* p = &g_pslot[s1 & 1][lane + i * 32];
                uint4 v2;
                do { v2 = ld_rlx4(p); } while (v2.w - base2 < s1);
                pk[i]  = ((unsigned long long)v2.y << 32) | v2.x;
                lsm[i] = __uint_as_float(v2.z);
            }
            unsigned long long m = pk[0];
#pragma unroll
            for (int i = 1; i < 4; i++) m = pk[i] > m ? pk[i] : m;
#pragma unroll
            for (int o = 16; o; o >>= 1) {
                unsigned long long other = __shfl_xor_sync(0xffffffffu, m, o);
                m = other > m ? other : m;
            }
            float gmax = sortable2f((unsigned)(m >> 32));
            float part = 0.f;
#pragma unroll
            for (int i = 0; i < 4; i++)
                part += lsm[i] * expf(sortable2f((unsigned)(pk[i] >> 32)) - gmax);
            part = warp_sum(part);
            if (lane == 0) {
                red_s[0] = gmax;
                red_s[1] = logf(part);
                red_s[2] = __uint_as_float(
                    0xFFFFFFFFu - (unsigned)(m & 0xFFFFFFFFull));
            }
        }
        __syncthreads();                // red_s ready
        float gmax = red_s[0], lse = red_s[1];
        prev_idx = (int)__float_as_uint(red_s[2]);
        if (tid < ORPB)
            out[(size_t)s * OUTSZ + bid * ORPB + tid] = ls[tid] - gmax - lse;
    }
}

// ---------------- launch ----------------------------------------------------
extern "C" void kernel_launch(void* const* d_in, const int* in_sizes, int n_in,
                              void* d_out, int out_size) {
    const float* input   = (const float*)d_in[0];
    const float* enc_Wih = (const float*)d_in[1];
    const float* enc_Whh = (const float*)d_in[2];
    const float* enc_bih = (const float*)d_in[3];
    const float* enc_bhh = (const float*)d_in[4];
    const float* dec_Wih = (const float*)d_in[5];
    const float* dec_Whh = (const float*)d_in[6];
    const float* dec_bih = (const float*)d_in[7];
    const float* dec_bhh = (const float*)d_in[8];
    const float* W_out   = (const float*)d_in[9];
    const float* b_out   = (const float*)d_in[10];
    float* out = (float*)d_out;

    static const int kDynSmem = 16 * HID * sizeof(__half)   // ws16   64KB
                              + HID * sizeof(__half);       // hstage  4KB
    cudaFuncSetAttribute(rnn_kernel,
                         cudaFuncAttributeMaxDynamicSharedMemorySize, kDynSmem);

    conv_x_kernel<<<(SEQ * INSZ / 4 + 255) / 256, 256>>>(input);
    conv_w_kernel<<<(G3 * INSZ / 4 + 255) / 256, 256>>>(enc_Wih);
    conv_wout_kernel<<<(OUTSZ * HID / 8 + 255) / 256, 256>>>(W_out);

    dim3 g1(G3 / 128, SEQ / 128);   // 48 x 4
    gemm_wmma_kernel<<<g1, 256>>>();

    rnn_kernel<<<NB, NT, kDynSmem>>>(enc_Whh, enc_bih, enc_bhh,
                                     dec_Wih, dec_Whh, dec_bih, dec_bhh,
                                     b_out, out);
}